// round 13
// baseline (speedup 1.0000x reference)
#include <cuda_runtime.h>
#include <cstdint>
#include <math.h>

#define T    2048
#define HD   1024
#define ID   2048
#define NE   8

// ---------------- scratch (__device__ globals; no allocation allowed) ----------------
__device__ float g_H [(size_t)NE * T * ID];   // routed h = silu(g)*u
__device__ float g_SH[(size_t)T * ID];        // shared h
__device__ int   g_tok[NE * T];
__device__ float g_wt [NE * T];
__device__ int   g_cnt[NE];
__device__ float g_sump[NE];
__device__ float g_lse2[1];

// ---------------- small kernels ----------------
__global__ void k_reset() {
    int i = threadIdx.x;
    if (i < NE) { g_cnt[i] = 0; g_sump[i] = 0.f; }
    if (i == 0) g_lse2[0] = 0.f;
}

__global__ void k_router(const float* __restrict__ x, const float* __restrict__ rw) {
    int t = blockIdx.x, tid = threadIdx.x;
    float acc[NE];
#pragma unroll
    for (int e = 0; e < NE; e++) acc[e] = 0.f;
    const float* xr = x + (size_t)t * HD;
    for (int j = tid; j < HD; j += 128) {
        float xv = xr[j];
        const float* r = rw + (size_t)j * NE;
#pragma unroll
        for (int e = 0; e < NE; e++) acc[e] += xv * r[e];
    }
    __shared__ float sm[NE][128];
#pragma unroll
    for (int e = 0; e < NE; e++) sm[e][tid] = acc[e];
    __syncthreads();
    for (int s = 64; s > 0; s >>= 1) {
        if (tid < s)
#pragma unroll
            for (int e = 0; e < NE; e++) sm[e][tid] += sm[e][tid + s];
        __syncthreads();
    }
    if (tid == 0) {
        float l[NE];
#pragma unroll
        for (int e = 0; e < NE; e++) l[e] = sm[e][0];
        float m = l[0];
#pragma unroll
        for (int e = 1; e < NE; e++) m = fmaxf(m, l[e]);
        float p[NE], sum = 0.f;
#pragma unroll
        for (int e = 0; e < NE; e++) { p[e] = expf(l[e] - m); sum += p[e]; }
        float inv = 1.f / sum;
#pragma unroll
        for (int e = 0; e < NE; e++) p[e] *= inv;
        float lse = m + logf(sum);
        atomicAdd(&g_lse2[0], lse * lse);
#pragma unroll
        for (int e = 0; e < NE; e++) atomicAdd(&g_sump[e], p[e]);
        int i0 = 0;
#pragma unroll
        for (int e = 1; e < NE; e++) if (p[e] > p[i0]) i0 = e;
        int i1 = -1;
#pragma unroll
        for (int e = 0; e < NE; e++) {
            if (e == i0) continue;
            if (i1 < 0 || p[e] > p[i1]) i1 = e;
        }
        float w0 = p[i0], w1 = p[i1], s2 = 1.f / (p[i0] + p[i1]);
        w0 *= s2; w1 *= s2;
        int q0 = atomicAdd(&g_cnt[i0], 1);
        g_tok[i0 * T + q0] = t; g_wt[i0 * T + q0] = w0;
        int q1 = atomicAdd(&g_cnt[i1], 1);
        g_tok[i1 * T + q1] = t; g_wt[i1 * T + q1] = w1;
    }
}

__global__ void k_aux(float* __restrict__ out) {
    float fp = 0.f;
#pragma unroll
    for (int e = 0; e < NE; e++)
        fp += ((float)g_cnt[e] / (float)(T * 2)) * (g_sump[e] / (float)T);
    out[0] = 0.01f * (float)NE * fp + 0.001f * (g_lse2[0] / (float)T);
}

// ---------------- tf32 tensor-core GEMM (mma.sync, pair-interleaved smem) ----------------
__device__ __forceinline__ uint32_t to_tf32(float f) {
    uint32_t r; asm("cvt.rna.tf32.f32 %0, %1;" : "=r"(r) : "f"(f)); return r;
}

#define MMA_TF32(d, a, b)                                                      \
    asm volatile(                                                              \
        "mma.sync.aligned.m16n8k8.row.col.f32.tf32.tf32.f32 "                  \
        "{%0,%1,%2,%3},{%4,%5,%6,%7},{%8,%9},{%0,%1,%2,%3};"                   \
        : "+f"((d)[0]), "+f"((d)[1]), "+f"((d)[2]), "+f"((d)[3])               \
        : "r"((a)[0]), "r"((a)[1]), "r"((a)[2]), "r"((a)[3]),                  \
          "r"((b)[0]), "r"((b)[1]))

// A pair layout: word(rp, k, h) = rp*40 + k*2 + h, rp = (mrow16)*8 + (row&7),
//   h=0 -> row, h=1 -> row+8.  (64 rp) * 40 = 2560 words / buffer.
// B pair layout: word(p8, n, h) = p8*264 + n*2 + h, p8 indexes k-pairs over
//   k in {0..3, 8..11}, h=0 -> B[k][n], h=1 -> B[k+4][n]. 8*264 = 2112 words.
#define A_W 2560
#define B_W 2112

// C[m,n] = sum_k A[row(m),k] * B[k,n]; block 128x128, BK=16, 512 threads,
// 16 warps in 4x4 grid of 32x32 tiles, double-buffered pair-interleaved smem.
// GATHER: A rows via toks. SCATTER: atomicAdd(out[tok], w*acc). FUSED: B2=up,
// epilogue stores silu(g)*u.
template <bool GATHER, bool SCATTER, bool FUSED>
__global__ __launch_bounds__(512, 1)
void k_gemm(const float* __restrict__ A, int lda, size_t strideA,
            const float* __restrict__ B, const float* __restrict__ B2,
            int ldb, size_t strideB,
            float* __restrict__ C, int ldc, size_t strideC,
            const int* __restrict__ cnt, int Mfixed, int K,
            const int* __restrict__ tokall, const float* __restrict__ wtall) {
    extern __shared__ uint32_t smem[];
    uint32_t* Asm  = smem;                          // 2 * A_W
    uint32_t* Bsm  = smem + 2 * A_W;                // 2 * B_W
    uint32_t* B2sm = smem + 2 * A_W + 2 * B_W;      // 2 * B_W (FUSED only)

    int e = blockIdx.z;
    int M = cnt ? cnt[e] : Mfixed;
    int m0 = blockIdx.x * 128;
    if (m0 >= M) return;
    int n0 = blockIdx.y * 128;

    const float* Ap  = A + (size_t)e * strideA;
    const float* Bp  = B + (size_t)e * strideB;
    const float* B2p = FUSED ? (B2 + (size_t)e * strideB) : nullptr;
    float* Cp = C + (size_t)e * strideC;
    const int*   toks = tokall ? tokall + e * T : nullptr;
    const float* wts  = wtall  ? wtall  + e * T : nullptr;

    int tid = threadIdx.x;
    int lane = tid & 31, wid = tid >> 5;
    int wm = wid & 3;        // 0..3 -> 32 rows
    int wn = wid >> 2;       // 0..3 -> 32 cols
    int grp = lane >> 2, tg = lane & 3;
    bool isA = (tid < 256);

    // ---- producer mappings ----
    // A-task (+ up-B task when FUSED): tid 0..255.  gate-B task: tid 256..511.
    const float *aP0 = nullptr, *aP1 = nullptr, *uP0 = nullptr, *uP1 = nullptr;
    const float *bP0 = nullptr, *bP1 = nullptr;
    uint32_t aw = 0, uw = 0, bw = 0;
    {
        int i = isA ? tid : (tid - 256);
        if (isA) {
            int rp = i >> 2;                 // 0..63
            int ks = (i & 3) << 2;           // 0,4,8,12
            int r0 = ((rp >> 3) << 4) + (rp & 7);
            int s0 = m0 + r0;      s0 = (s0 < M) ? s0 : (M - 1);
            int s1 = m0 + r0 + 8;  s1 = (s1 < M) ? s1 : (M - 1);
            int gr0 = GATHER ? toks[s0] : s0;
            int gr1 = GATHER ? toks[s1] : s1;
            aP0 = Ap + (size_t)gr0 * lda + ks;
            aP1 = Ap + (size_t)gr1 * lda + ks;
            aw = rp * 40 + ks * 2;
        }
        // B-style task (gate for tid>=256, up for tid<256 when FUSED)
        int ng = i & 31, p8 = (i >> 5) & 7;
        int kB = (p8 & 3) + ((p8 >> 2) << 3);
        int nn = ng << 2;
        if (!isA) {
            bP0 = Bp + (size_t)kB * ldb + n0 + nn;
            bP1 = Bp + (size_t)(kB + 4) * ldb + n0 + nn;
            bw = p8 * 264 + nn * 2;
        } else if (FUSED) {
            uP0 = B2p + (size_t)kB * ldb + n0 + nn;
            uP1 = B2p + (size_t)(kB + 4) * ldb + n0 + nn;
            uw = p8 * 264 + nn * 2;
        }
    }

    float accg[2][4][4];
    float accu[2][4][4];
#pragma unroll
    for (int i = 0; i < 2; i++)
#pragma unroll
        for (int j = 0; j < 4; j++)
#pragma unroll
            for (int k = 0; k < 4; k++) { accg[i][j][k] = 0.f; if (FUSED) accu[i][j][k] = 0.f; }

    int ktiles = K / 16;
    float4 la0, la1, lu0, lu1, lb0, lb1;

#define LOAD_SLAB(kt)                                                             \
    do {                                                                          \
        if (isA) {                                                                \
            la0 = *(const float4*)(aP0 + (kt) * 16);                              \
            la1 = *(const float4*)(aP1 + (kt) * 16);                              \
            if (FUSED) {                                                          \
                lu0 = *(const float4*)(uP0 + (size_t)((kt) * 16) * ldb);          \
                lu1 = *(const float4*)(uP1 + (size_t)((kt) * 16) * ldb);          \
            }                                                                     \
        } else {                                                                  \
            lb0 = *(const float4*)(bP0 + (size_t)((kt) * 16) * ldb);              \
            lb1 = *(const float4*)(bP1 + (size_t)((kt) * 16) * ldb);              \
        }                                                                         \
    } while (0)

#define STS_SLAB(bf)                                                              \
    do {                                                                          \
        if (isA) {                                                                \
            uint32_t* d = &Asm[(bf) * A_W + aw];                                  \
            uint4 v1 = { to_tf32(la0.x), to_tf32(la1.x), to_tf32(la0.y), to_tf32(la1.y) }; \
            uint4 v2 = { to_tf32(la0.z), to_tf32(la1.z), to_tf32(la0.w), to_tf32(la1.w) }; \
            *(uint4*)(d) = v1; *(uint4*)(d + 4) = v2;                             \
            if (FUSED) {                                                          \
                uint32_t* u = &B2sm[(bf) * B_W + uw];                             \
                uint4 w1 = { to_tf32(lu0.x), to_tf32(lu1.x), to_tf32(lu0.y), to_tf32(lu1.y) }; \
                uint4 w2 = { to_tf32(lu0.z), to_tf32(lu1.z), to_tf32(lu0.w), to_tf32(lu1.w) }; \
                *(uint4*)(u) = w1; *(uint4*)(u + 4) = w2;                         \
            }                                                                     \
        } else {                                                                  \
            uint32_t* d = &Bsm[(bf) * B_W + bw];                                  \
            uint4 v1 = { to_tf32(lb0.x), to_tf32(lb1.x), to_tf32(lb0.y), to_tf32(lb1.y) }; \
            uint4 v2 = { to_tf32(lb0.z), to_tf32(lb1.z), to_tf32(lb0.w), to_tf32(lb1.w) }; \
            *(uint4*)(d) = v1; *(uint4*)(d + 4) = v2;                             \
        }                                                                         \
    } while (0)

    LOAD_SLAB(0);
    int buf = 0;
    STS_SLAB(0);
    __syncthreads();

    for (int kt = 0; kt < ktiles; kt++) {
        bool has = (kt + 1 < ktiles);
        if (has) LOAD_SLAB(kt + 1);
        // compute on current buffer
        uint32_t aofs = buf * A_W;
        uint32_t bofs = buf * B_W;
#pragma unroll
        for (int kk = 0; kk < 16; kk += 8) {
            uint32_t a[2][4], bg[4][2], bu[4][2];
#pragma unroll
            for (int mt = 0; mt < 2; mt++) {
                uint32_t w = aofs + ((wm * 2 + mt) * 8 + grp) * 40 + (kk + tg) * 2;
                uint2 p0 = *(const uint2*)&Asm[w];
                uint2 p1 = *(const uint2*)&Asm[w + 8];
                a[mt][0] = p0.x; a[mt][1] = p0.y; a[mt][2] = p1.x; a[mt][3] = p1.y;
            }
#pragma unroll
            for (int nt = 0; nt < 4; nt++) {
                int c = wn * 32 + nt * 8 + grp;
                uint32_t w = bofs + ((kk >> 1) + tg) * 264 + c * 2;
                uint2 r = *(const uint2*)&Bsm[w];
                bg[nt][0] = r.x; bg[nt][1] = r.y;
                if (FUSED) {
                    uint2 s = *(const uint2*)&B2sm[w];
                    bu[nt][0] = s.x; bu[nt][1] = s.y;
                }
            }
#pragma unroll
            for (int mt = 0; mt < 2; mt++)
#pragma unroll
                for (int nt = 0; nt < 4; nt++) {
                    MMA_TF32(accg[mt][nt], a[mt], bg[nt]);
                    if (FUSED) MMA_TF32(accu[mt][nt], a[mt], bu[nt]);
                }
        }
        if (has) {
            buf ^= 1;
            STS_SLAB(buf);
            __syncthreads();
        }
    }

    // ---- epilogue (identical to proven round-7 version) ----
#pragma unroll
    for (int mt = 0; mt < 2; mt++) {
        int rbase = m0 + wm * 32 + mt * 16 + grp;
#pragma unroll
        for (int half = 0; half < 2; half++) {
            int r = rbase + half * 8;
            if (r < M) {
                if (SCATTER) {
                    int tok = toks[r];
                    float w = wts[r];
                    float* dst = C + (size_t)tok * ldc;
#pragma unroll
                    for (int nt = 0; nt < 4; nt++) {
                        int c = n0 + wn * 32 + nt * 8 + tg * 2;
                        atomicAdd(dst + c,     w * accg[mt][nt][half * 2 + 0]);
                        atomicAdd(dst + c + 1, w * accg[mt][nt][half * 2 + 1]);
                    }
                } else if (FUSED) {
                    float* dst = Cp + (size_t)r * ldc;
#pragma unroll
                    for (int nt = 0; nt < 4; nt++) {
                        int c = n0 + wn * 32 + nt * 8 + tg * 2;
#pragma unroll
                        for (int j = 0; j < 2; j++) {
                            float gv = accg[mt][nt][half * 2 + j];
                            float uv = accu[mt][nt][half * 2 + j];
                            dst[c + j] = gv * uv / (1.f + __expf(-gv));
                        }
                    }
                } else {
                    float* dst = Cp + (size_t)r * ldc;
#pragma unroll
                    for (int nt = 0; nt < 4; nt++) {
                        int c = n0 + wn * 32 + nt * 8 + tg * 2;
                        dst[c]     = accg[mt][nt][half * 2 + 0];
                        dst[c + 1] = accg[mt][nt][half * 2 + 1];
                    }
                }
            }
        }
    }
#undef LOAD_SLAB
#undef STS_SLAB
}

// ---------------- launch ----------------
extern "C" void kernel_launch(void* const* d_in, const int* in_sizes, int n_in,
                              void* d_out, int out_size) {
    const float* x  = (const float*)d_in[0];
    const float* rw = (const float*)d_in[1];
    const float* eg = (const float*)d_in[2];
    const float* eu = (const float*)d_in[3];
    const float* ed = (const float*)d_in[4];
    const float* sg = (const float*)d_in[5];
    const float* su = (const float*)d_in[6];
    const float* sd = (const float*)d_in[7];
    float* out = (float*)d_out;

    float *pH, *pSH, *pwt;
    int *ptok, *pcnt;
    cudaGetSymbolAddress((void**)&pH,   g_H);
    cudaGetSymbolAddress((void**)&pSH,  g_SH);
    cudaGetSymbolAddress((void**)&ptok, g_tok);
    cudaGetSymbolAddress((void**)&pwt,  g_wt);
    cudaGetSymbolAddress((void**)&pcnt, g_cnt);
    (void)in_sizes; (void)n_in;

    const int SM_B = (2 * A_W + 2 * B_W) * 4;   // 37376 B
    const int SM_F = (2 * A_W + 4 * B_W) * 4;   // 54272 B
    cudaFuncSetAttribute(k_gemm<false, false, true>,
                         cudaFuncAttributeMaxDynamicSharedMemorySize, SM_F);
    cudaFuncSetAttribute(k_gemm<true, false, true>,
                         cudaFuncAttributeMaxDynamicSharedMemorySize, SM_F);
    cudaFuncSetAttribute(k_gemm<false, false, false>,
                         cudaFuncAttributeMaxDynamicSharedMemorySize, SM_B);
    cudaFuncSetAttribute(k_gemm<false, true, false>,
                         cudaFuncAttributeMaxDynamicSharedMemorySize, SM_B);

    k_reset<<<1, 32>>>();
    k_router<<<T, 128>>>(x, rw);
    if (out_size > T * HD) k_aux<<<1, 1>>>(out + (size_t)T * HD);

    // ---- shared expert: fused gate+up -> h, then down (stores, initializes out) ----
    k_gemm<false, false, true><<<dim3(T / 128, ID / 128, 1), 512, SM_F>>>(
        x, HD, 0, sg, su, ID, 0, pSH, ID, 0, nullptr, T, HD, nullptr, nullptr);
    k_gemm<false, false, false><<<dim3(T / 128, HD / 128, 1), 512, SM_B>>>(
        pSH, ID, 0, sd, nullptr, HD, 0, out, HD, 0, nullptr, T, ID, nullptr, nullptr);

    // ---- routed experts: gathered fused gate+up -> h, then scatter down ----
    k_gemm<true, false, true><<<dim3(T / 128, ID / 128, NE), 512, SM_F>>>(
        x, HD, 0, eg, eu, ID, (size_t)HD * ID, pH, ID, (size_t)T * ID,
        pcnt, T, HD, ptok, nullptr);
    k_gemm<false, true, false><<<dim3(T / 128, HD / 128, NE), 512, SM_B>>>(
        pH, ID, (size_t)T * ID, ed, nullptr, HD, (size_t)ID * HD, out, HD, 0,
        pcnt, T, ID, ptok, pwt);
}

// round 14
// speedup vs baseline: 1.4484x; 1.4484x over previous
#include <cuda_runtime.h>
#include <cstdint>
#include <math.h>

#define T    2048
#define HD   1024
#define ID   2048
#define NE   8

// ---------------- scratch (__device__ globals; no allocation allowed) ----------------
__device__ float g_H [(size_t)NE * T * ID];   // routed h = silu(g)*u
__device__ float g_SH[(size_t)T * ID];        // shared h
__device__ int   g_tok[NE * T];
__device__ float g_wt [NE * T];
__device__ int   g_cnt[NE];
__device__ float g_sump[NE];
__device__ float g_lse2[1];

// ---------------- small kernels ----------------
__global__ void k_reset() {
    int i = threadIdx.x;
    if (i < NE) { g_cnt[i] = 0; g_sump[i] = 0.f; }
    if (i == 0) g_lse2[0] = 0.f;
}

__global__ void k_router(const float* __restrict__ x, const float* __restrict__ rw) {
    int t = blockIdx.x, tid = threadIdx.x;
    float acc[NE];
#pragma unroll
    for (int e = 0; e < NE; e++) acc[e] = 0.f;
    const float* xr = x + (size_t)t * HD;
    for (int j = tid; j < HD; j += 128) {
        float xv = xr[j];
        const float* r = rw + (size_t)j * NE;
#pragma unroll
        for (int e = 0; e < NE; e++) acc[e] += xv * r[e];
    }
    __shared__ float sm[NE][128];
#pragma unroll
    for (int e = 0; e < NE; e++) sm[e][tid] = acc[e];
    __syncthreads();
    for (int s = 64; s > 0; s >>= 1) {
        if (tid < s)
#pragma unroll
            for (int e = 0; e < NE; e++) sm[e][tid] += sm[e][tid + s];
        __syncthreads();
    }
    if (tid == 0) {
        float l[NE];
#pragma unroll
        for (int e = 0; e < NE; e++) l[e] = sm[e][0];
        float m = l[0];
#pragma unroll
        for (int e = 1; e < NE; e++) m = fmaxf(m, l[e]);
        float p[NE], sum = 0.f;
#pragma unroll
        for (int e = 0; e < NE; e++) { p[e] = expf(l[e] - m); sum += p[e]; }
        float inv = 1.f / sum;
#pragma unroll
        for (int e = 0; e < NE; e++) p[e] *= inv;
        float lse = m + logf(sum);
        atomicAdd(&g_lse2[0], lse * lse);
#pragma unroll
        for (int e = 0; e < NE; e++) atomicAdd(&g_sump[e], p[e]);
        int i0 = 0;
#pragma unroll
        for (int e = 1; e < NE; e++) if (p[e] > p[i0]) i0 = e;
        int i1 = -1;
#pragma unroll
        for (int e = 0; e < NE; e++) {
            if (e == i0) continue;
            if (i1 < 0 || p[e] > p[i1]) i1 = e;
        }
        float w0 = p[i0], w1 = p[i1], s2 = 1.f / (p[i0] + p[i1]);
        w0 *= s2; w1 *= s2;
        int q0 = atomicAdd(&g_cnt[i0], 1);
        g_tok[i0 * T + q0] = t; g_wt[i0 * T + q0] = w0;
        int q1 = atomicAdd(&g_cnt[i1], 1);
        g_tok[i1 * T + q1] = t; g_wt[i1 * T + q1] = w1;
    }
}

__global__ void k_aux(float* __restrict__ out) {
    float fp = 0.f;
#pragma unroll
    for (int e = 0; e < NE; e++)
        fp += ((float)g_cnt[e] / (float)(T * 2)) * (g_sump[e] / (float)T);
    out[0] = 0.01f * (float)NE * fp + 0.001f * (g_lse2[0] / (float)T);
}

// ---------------- tf32 tensor-core GEMM (mma.sync), BK=32, R7-proven layout ----------------
__device__ __forceinline__ uint32_t to_tf32(float f) {
    uint32_t r; asm("cvt.rna.tf32.f32 %0, %1;" : "=r"(r) : "f"(f)); return r;
}

#define MMA_TF32(d, a, b)                                                      \
    asm volatile(                                                              \
        "mma.sync.aligned.m16n8k8.row.col.f32.tf32.tf32.f32 "                  \
        "{%0,%1,%2,%3},{%4,%5,%6,%7},{%8,%9},{%0,%1,%2,%3};"                   \
        : "+f"((d)[0]), "+f"((d)[1]), "+f"((d)[2]), "+f"((d)[3])               \
        : "r"((a)[0]), "r"((a)[1]), "r"((a)[2]), "r"((a)[3]),                  \
          "r"((b)[0]), "r"((b)[1]))

// A: Asm[row*36 + k], row<128, k<32 (stride 36 => frag banks 4*grp+tg, conflict-free)
// B: Bsm[k*136 + n],  k<32,  n<128 (proven stride 136)
#define A_W 4608    // 128*36
#define B_W 4352    // 32*136

// Shared fragment-compute macro body is duplicated inline in both kernels below.
// Block tile 128x128, BK=32, 512 threads, 16 warps in 4x4 grid of 32x32 tiles.

// ---- merged fused gate+up: z=0..7 routed experts (gather), z=8 shared expert ----
__global__ __launch_bounds__(512, 1)
void k_gu(const float* __restrict__ x,
          const float* __restrict__ eg, const float* __restrict__ eu,
          const float* __restrict__ sg, const float* __restrict__ su,
          float* __restrict__ H, float* __restrict__ SH,
          const int* __restrict__ cnt, const int* __restrict__ tokall) {
    extern __shared__ uint32_t smem[];
    uint32_t* Asm  = smem;                 // 2 * A_W
    uint32_t* Bsm  = smem + 2 * A_W;       // 2 * B_W
    uint32_t* B2sm = smem + 2 * A_W + 2 * B_W;

    int e = blockIdx.z;
    bool routed = (e < NE);
    int M = routed ? cnt[e] : T;
    int m0 = blockIdx.x * 128;
    if (m0 >= M) return;
    int n0 = blockIdx.y * 128;

    const float* Bp  = routed ? eg + (size_t)e * HD * ID : sg;
    const float* B2p = routed ? eu + (size_t)e * HD * ID : su;
    float* Cp = routed ? H + (size_t)e * T * ID : SH;
    const int* toks = routed ? tokall + e * T : nullptr;

    int tid = threadIdx.x;
    int lane = tid & 31, wid = tid >> 5;
    int wm = wid & 3, wn = wid >> 2;
    int grp = lane >> 2, tg = lane & 3;

    // producers: every thread loads A(8k), Bg(8n), Bu(8n) per slab
    int aRow = tid >> 2, aOff = (tid & 3) * 8;
    int sRow;
    {
        int s = m0 + aRow; s = (s < M) ? s : (M - 1);
        sRow = routed ? toks[s] : s;
    }
    const float* aPtr = x + (size_t)sRow * HD + aOff;
    int bK = tid >> 4, bN = (tid & 15) * 8;
    const float* bPtr  = Bp  + (size_t)bK * ID + n0 + bN;
    const float* b2Ptr = B2p + (size_t)bK * ID + n0 + bN;
    uint32_t aw = aRow * 36 + aOff;
    uint32_t bw = bK * 136 + bN;

    float accg[2][4][4], accu[2][4][4];
#pragma unroll
    for (int i = 0; i < 2; i++)
#pragma unroll
        for (int j = 0; j < 4; j++)
#pragma unroll
            for (int k = 0; k < 4; k++) { accg[i][j][k] = 0.f; accu[i][j][k] = 0.f; }

    const int nslabs = HD / 32;
    float4 a0, a1, b0, b1, c0, c1;
#define LOAD_SLAB(kt)                                                          \
    do {                                                                       \
        const float* _a = aPtr + (kt) * 32;                                    \
        a0 = *(const float4*)_a; a1 = *(const float4*)(_a + 4);                \
        const float* _b = bPtr + (size_t)(kt) * 32 * ID;                       \
        b0 = *(const float4*)_b; b1 = *(const float4*)(_b + 4);                \
        const float* _c = b2Ptr + (size_t)(kt) * 32 * ID;                      \
        c0 = *(const float4*)_c; c1 = *(const float4*)(_c + 4);                \
    } while (0)
#define STS_SLAB(bf)                                                           \
    do {                                                                       \
        uint32_t* d = &Asm[(bf) * A_W + aw];                                   \
        d[0]=to_tf32(a0.x); d[1]=to_tf32(a0.y); d[2]=to_tf32(a0.z); d[3]=to_tf32(a0.w); \
        d[4]=to_tf32(a1.x); d[5]=to_tf32(a1.y); d[6]=to_tf32(a1.z); d[7]=to_tf32(a1.w); \
        uint32_t* g = &Bsm[(bf) * B_W + bw];                                   \
        g[0]=to_tf32(b0.x); g[1]=to_tf32(b0.y); g[2]=to_tf32(b0.z); g[3]=to_tf32(b0.w); \
        g[4]=to_tf32(b1.x); g[5]=to_tf32(b1.y); g[6]=to_tf32(b1.z); g[7]=to_tf32(b1.w); \
        uint32_t* u = &B2sm[(bf) * B_W + bw];                                  \
        u[0]=to_tf32(c0.x); u[1]=to_tf32(c0.y); u[2]=to_tf32(c0.z); u[3]=to_tf32(c0.w); \
        u[4]=to_tf32(c1.x); u[5]=to_tf32(c1.y); u[6]=to_tf32(c1.z); u[7]=to_tf32(c1.w); \
    } while (0)

    LOAD_SLAB(0);
    int buf = 0;
    STS_SLAB(0);
    __syncthreads();

    for (int kt = 0; kt < nslabs; kt++) {
        bool has = (kt + 1 < nslabs);
        if (has) LOAD_SLAB(kt + 1);
        uint32_t aofs = buf * A_W, bofs = buf * B_W;
#pragma unroll
        for (int kk = 0; kk < 32; kk += 8) {
            uint32_t a[2][4], bg[4][2], bu[4][2];
#pragma unroll
            for (int mt = 0; mt < 2; mt++) {
                uint32_t r0 = aofs + (wm * 32 + mt * 16 + grp) * 36;
                a[mt][0] = Asm[r0 + kk + tg];
                a[mt][1] = Asm[r0 + 288 + kk + tg];
                a[mt][2] = Asm[r0 + kk + tg + 4];
                a[mt][3] = Asm[r0 + 288 + kk + tg + 4];
            }
#pragma unroll
            for (int nt = 0; nt < 4; nt++) {
                int c = wn * 32 + nt * 8 + grp;
                bg[nt][0] = Bsm[bofs + (kk + tg) * 136 + c];
                bg[nt][1] = Bsm[bofs + (kk + 4 + tg) * 136 + c];
                bu[nt][0] = B2sm[bofs + (kk + tg) * 136 + c];
                bu[nt][1] = B2sm[bofs + (kk + 4 + tg) * 136 + c];
            }
#pragma unroll
            for (int mt = 0; mt < 2; mt++)
#pragma unroll
                for (int nt = 0; nt < 4; nt++) {
                    MMA_TF32(accg[mt][nt], a[mt], bg[nt]);
                    MMA_TF32(accu[mt][nt], a[mt], bu[nt]);
                }
        }
        if (has) {
            buf ^= 1;
            STS_SLAB(buf);
            __syncthreads();
        }
    }

#pragma unroll
    for (int mt = 0; mt < 2; mt++) {
        int rbase = m0 + wm * 32 + mt * 16 + grp;
#pragma unroll
        for (int half = 0; half < 2; half++) {
            int r = rbase + half * 8;
            if (r < M) {
                float* dst = Cp + (size_t)r * ID;
#pragma unroll
                for (int nt = 0; nt < 4; nt++) {
                    int c = n0 + wn * 32 + nt * 8 + tg * 2;
#pragma unroll
                    for (int j = 0; j < 2; j++) {
                        float gv = accg[mt][nt][half * 2 + j];
                        float uv = accu[mt][nt][half * 2 + j];
                        dst[c + j] = gv * uv / (1.f + __expf(-gv));
                    }
                }
            }
        }
    }
#undef LOAD_SLAB
#undef STS_SLAB
}

// ---- merged down-proj: z=0..7 routed (weighted scatter), z=8 shared (w=1, tok=row) ----
__global__ __launch_bounds__(512, 1)
void k_down(const float* __restrict__ H, const float* __restrict__ SH,
            const float* __restrict__ ed, const float* __restrict__ sd,
            float* __restrict__ out,
            const int* __restrict__ cnt, const int* __restrict__ tokall,
            const float* __restrict__ wtall) {
    extern __shared__ uint32_t smem[];
    uint32_t* Asm = smem;              // 2 * A_W
    uint32_t* Bsm = smem + 2 * A_W;    // 2 * B_W

    int e = blockIdx.z;
    bool routed = (e < NE);
    int M = routed ? cnt[e] : T;
    int m0 = blockIdx.x * 128;
    if (m0 >= M) return;
    int n0 = blockIdx.y * 128;

    const float* Ap = routed ? H + (size_t)e * T * ID : SH;
    const float* Bp = routed ? ed + (size_t)e * ID * HD : sd;
    const int*   toks = routed ? tokall + e * T : nullptr;
    const float* wts  = routed ? wtall  + e * T : nullptr;

    int tid = threadIdx.x;
    int lane = tid & 31, wid = tid >> 5;
    int wm = wid & 3, wn = wid >> 2;
    int grp = lane >> 2, tg = lane & 3;

    int aRow = tid >> 2, aOff = (tid & 3) * 8;
    int sRow = m0 + aRow; sRow = (sRow < M) ? sRow : (M - 1);
    const float* aPtr = Ap + (size_t)sRow * ID + aOff;
    int bK = tid >> 4, bN = (tid & 15) * 8;
    const float* bPtr = Bp + (size_t)bK * HD + n0 + bN;
    uint32_t aw = aRow * 36 + aOff;
    uint32_t bw = bK * 136 + bN;

    float accg[2][4][4];
#pragma unroll
    for (int i = 0; i < 2; i++)
#pragma unroll
        for (int j = 0; j < 4; j++)
#pragma unroll
            for (int k = 0; k < 4; k++) accg[i][j][k] = 0.f;

    const int nslabs = ID / 32;
    float4 a0, a1, b0, b1;
#define LOAD_SLAB(kt)                                                          \
    do {                                                                       \
        const float* _a = aPtr + (kt) * 32;                                    \
        a0 = *(const float4*)_a; a1 = *(const float4*)(_a + 4);                \
        const float* _b = bPtr + (size_t)(kt) * 32 * HD;                       \
        b0 = *(const float4*)_b; b1 = *(const float4*)(_b + 4);                \
    } while (0)
#define STS_SLAB(bf)                                                           \
    do {                                                                       \
        uint32_t* d = &Asm[(bf) * A_W + aw];                                   \
        d[0]=to_tf32(a0.x); d[1]=to_tf32(a0.y); d[2]=to_tf32(a0.z); d[3]=to_tf32(a0.w); \
        d[4]=to_tf32(a1.x); d[5]=to_tf32(a1.y); d[6]=to_tf32(a1.z); d[7]=to_tf32(a1.w); \
        uint32_t* g = &Bsm[(bf) * B_W + bw];                                   \
        g[0]=to_tf32(b0.x); g[1]=to_tf32(b0.y); g[2]=to_tf32(b0.z); g[3]=to_tf32(b0.w); \
        g[4]=to_tf32(b1.x); g[5]=to_tf32(b1.y); g[6]=to_tf32(b1.z); g[7]=to_tf32(b1.w); \
    } while (0)

    LOAD_SLAB(0);
    int buf = 0;
    STS_SLAB(0);
    __syncthreads();

    for (int kt = 0; kt < nslabs; kt++) {
        bool has = (kt + 1 < nslabs);
        if (has) LOAD_SLAB(kt + 1);
        uint32_t aofs = buf * A_W, bofs = buf * B_W;
#pragma unroll
        for (int kk = 0; kk < 32; kk += 8) {
            uint32_t a[2][4], bg[4][2];
#pragma unroll
            for (int mt = 0; mt < 2; mt++) {
                uint32_t r0 = aofs + (wm * 32 + mt * 16 + grp) * 36;
                a[mt][0] = Asm[r0 + kk + tg];
                a[mt][1] = Asm[r0 + 288 + kk + tg];
                a[mt][2] = Asm[r0 + kk + tg + 4];
                a[mt][3] = Asm[r0 + 288 + kk + tg + 4];
            }
#pragma unroll
            for (int nt = 0; nt < 4; nt++) {
                int c = wn * 32 + nt * 8 + grp;
                bg[nt][0] = Bsm[bofs + (kk + tg) * 136 + c];
                bg[nt][1] = Bsm[bofs + (kk + 4 + tg) * 136 + c];
            }
#pragma unroll
            for (int mt = 0; mt < 2; mt++)
#pragma unroll
                for (int nt = 0; nt < 4; nt++)
                    MMA_TF32(accg[mt][nt], a[mt], bg[nt]);
        }
        if (has) {
            buf ^= 1;
            STS_SLAB(buf);
            __syncthreads();
        }
    }

#pragma unroll
    for (int mt = 0; mt < 2; mt++) {
        int rbase = m0 + wm * 32 + mt * 16 + grp;
#pragma unroll
        for (int half = 0; half < 2; half++) {
            int r = rbase + half * 8;
            if (r < M) {
                int tok; float w;
                if (routed) { tok = toks[r]; w = wts[r]; }
                else        { tok = r;       w = 1.f; }
                float* dst = out + (size_t)tok * HD;
#pragma unroll
                for (int nt = 0; nt < 4; nt++) {
                    int c = n0 + wn * 32 + nt * 8 + tg * 2;
                    atomicAdd(dst + c,     w * accg[mt][nt][half * 2 + 0]);
                    atomicAdd(dst + c + 1, w * accg[mt][nt][half * 2 + 1]);
                }
            }
        }
    }
#undef LOAD_SLAB
#undef STS_SLAB
}

// ---------------- launch ----------------
extern "C" void kernel_launch(void* const* d_in, const int* in_sizes, int n_in,
                              void* d_out, int out_size) {
    const float* x  = (const float*)d_in[0];
    const float* rw = (const float*)d_in[1];
    const float* eg = (const float*)d_in[2];
    const float* eu = (const float*)d_in[3];
    const float* ed = (const float*)d_in[4];
    const float* sg = (const float*)d_in[5];
    const float* su = (const float*)d_in[6];
    const float* sd = (const float*)d_in[7];
    float* out = (float*)d_out;

    float *pH, *pSH, *pwt;
    int *ptok, *pcnt;
    cudaGetSymbolAddress((void**)&pH,   g_H);
    cudaGetSymbolAddress((void**)&pSH,  g_SH);
    cudaGetSymbolAddress((void**)&ptok, g_tok);
    cudaGetSymbolAddress((void**)&pwt,  g_wt);
    cudaGetSymbolAddress((void**)&pcnt, g_cnt);
    (void)in_sizes; (void)n_in;

    const int SM_GU   = (2 * A_W + 4 * B_W) * 4;  // 106496 B
    const int SM_DOWN = (2 * A_W + 2 * B_W) * 4;  //  71680 B
    cudaFuncSetAttribute(k_gu,   cudaFuncAttributeMaxDynamicSharedMemorySize, SM_GU);
    cudaFuncSetAttribute(k_down, cudaFuncAttributeMaxDynamicSharedMemorySize, SM_DOWN);

    k_reset<<<1, 32>>>();
    cudaMemsetAsync(out, 0, (size_t)T * HD * sizeof(float));
    k_router<<<T, 128>>>(x, rw);
    if (out_size > T * HD) k_aux<<<1, 1>>>(out + (size_t)T * HD);

    // merged fused gate+up (routed z=0..7 + shared z=8) -> h buffers
    k_gu<<<dim3(T / 128, ID / 128, NE + 1), 512, SM_GU>>>(
        x, eg, eu, sg, su, pH, pSH, pcnt, ptok);

    // merged down-proj (routed weighted scatter z=0..7 + shared z=8) -> out
    k_down<<<dim3(T / 128, HD / 128, NE + 1), 512, SM_DOWN>>>(
        pH, pSH, ed, sd, out, pcnt, ptok, pwt);
}